// round 3
// baseline (speedup 1.0000x reference)
#include <cuda_runtime.h>
#include <math.h>
#include <cstdint>

#define B_ 2
#define L_ 2048
#define E_ 1024
#define H_ 16
#define D_ 64
#define M_ (B_*L_)   // 4096

// Scratch (allocation-free rule: __device__ globals). 64 MB total.
__device__ float g_q[B_*H_*L_*D_];   // [B,H,L,D]
__device__ float g_k[B_*H_*L_*D_];   // [B,H,L,D]
__device__ float g_v[B_*H_*L_*D_];   // [B,H,L,D]
__device__ float g_o[B_*L_*E_];      // [B,L,E]

// ---------------------------------------------------------------------------
// NT GEMM:  C = A(MxK) @ W(NxK)^T + bias
// MODE 0: A = g_o (device global), C = param, row-major [M,N]   -- out proj
// MODE 1/2/3: A = param, C = g_q/g_k/g_v scatter to [B,H,L,D]   -- projections
// ---------------------------------------------------------------------------
template<int BM,int BN,int BK,int TM,int TN,int MODE>
__global__ void __launch_bounds__((BM/TM)*(BN/TN))
gemm_nt(const float* __restrict__ A_param, const float* __restrict__ W,
        const float* __restrict__ bias, float* __restrict__ C_param,
        int M, int N, int K)
{
    constexpr int TX = BN/TN, TY = BM/TM, NT = TX*TY;
    __shared__ float As[BK][BM+4];   // +4 pad: kills transpose-store conflicts
    __shared__ float Bs[BK][BN+4];

    const float* A = (MODE == 0) ? (const float*)g_o : A_param;
    float* C = (MODE == 0) ? C_param
             : (MODE == 1) ? (float*)g_q
             : (MODE == 2) ? (float*)g_k
             :               (float*)g_v;

    const int m0 = blockIdx.y * BM;
    const int n0 = blockIdx.x * BN;
    const int tid = threadIdx.x;
    const int tx = tid % TX, ty = tid / TX;

    float acc[TM][TN];
#pragma unroll
    for (int i = 0; i < TM; i++)
#pragma unroll
        for (int j = 0; j < TN; j++) acc[i][j] = 0.f;

    for (int k0 = 0; k0 < K; k0 += BK) {
#pragma unroll
        for (int i = tid; i < BM*BK; i += NT) {
            int r = i / BK, c = i % BK;
            As[c][r] = A[(long)(m0 + r) * K + k0 + c];
        }
#pragma unroll
        for (int i = tid; i < BN*BK; i += NT) {
            int r = i / BK, c = i % BK;
            Bs[c][r] = W[(long)(n0 + r) * K + k0 + c];
        }
        __syncthreads();

#pragma unroll
        for (int kk = 0; kk < BK; kk++) {
            float a[TM], b[TN];
#pragma unroll
            for (int i = 0; i < TM; i += 4)
                *reinterpret_cast<float4*>(&a[i]) =
                    *reinterpret_cast<const float4*>(&As[kk][ty*TM + i]);
#pragma unroll
            for (int j = 0; j < TN; j += 4)
                *reinterpret_cast<float4*>(&b[j]) =
                    *reinterpret_cast<const float4*>(&Bs[kk][tx*TN + j]);
#pragma unroll
            for (int i = 0; i < TM; i++)
#pragma unroll
                for (int j = 0; j < TN; j++)
                    acc[i][j] = fmaf(a[i], b[j], acc[i][j]);
        }
        __syncthreads();
    }

#pragma unroll
    for (int i = 0; i < TM; i++) {
        const int m = m0 + ty*TM + i;
#pragma unroll
        for (int j = 0; j < TN; j++) {
            const int n = n0 + tx*TN + j;
            float v = acc[i][j] + (bias ? bias[n] : 0.f);
            if (MODE == 0) {
                C[(long)m * N + n] = v;
            } else {                          // scatter to [B,H,L,D]
                int b = m >> 11, l = m & (L_-1);
                int h = n >> 6,  d = n & (D_-1);
                C[(((long)(b*H_ + h) * L_ + l) * D_) + d] = v;
            }
        }
    }
}

// ---------------------------------------------------------------------------
// Fused flash attention (fp32, online softmax). No P materialization:
// PV computed via shuffle-broadcast of P within each 16-lane row group.
// Block: 256 threads, 64 q-rows per block for one (b,h); 64-wide KV tiles.
// Static smem: Qs[64][64] + Ks[64][64] (d-major) + Vs[64][64] = 48 KB exactly.
// ---------------------------------------------------------------------------
#define FBM 64
#define FBN 64

__global__ void __launch_bounds__(256)
flash_attn()
{
    __shared__ float Qs[D_][FBM];    // [d][i]
    __shared__ float Ks[D_][FBN];    // [d][j]
    __shared__ float Vs[FBN][D_];    // [j][d]

    const int bh  = blockIdx.y;
    const int b   = bh / H_, h = bh % H_;
    const int i0g = blockIdx.x * FBM;
    const float* Qb = g_q + ((long)bh * L_ + i0g) * D_;
    const float* Kb = g_k + (long)bh * L_ * D_;
    const float* Vb = g_v + (long)bh * L_ * D_;

    const int tid = threadIdx.x;
    const int tx = tid % 16, ty = tid / 16;
    const int i0  = ty * 4;         // local q rows
    const int c0l = tx * 4;         // local cols (j for S, d for O)

    // Load Q tile transposed [d][i]
    {
        int r  = tid >> 2;
        int cb = (tid & 3) * 16;
#pragma unroll
        for (int c = 0; c < 16; c += 4) {
            float4 v4 = *reinterpret_cast<const float4*>(&Qb[(long)r*D_ + cb + c]);
            Qs[cb+c+0][r] = v4.x; Qs[cb+c+1][r] = v4.y;
            Qs[cb+c+2][r] = v4.z; Qs[cb+c+3][r] = v4.w;
        }
    }

    float acc[4][4] = {};
    float m_i[4], l_i[4];
#pragma unroll
    for (int r = 0; r < 4; r++) { m_i[r] = -1e30f; l_i[r] = 0.f; }

    const float scale = 0.125f;     // 1/sqrt(64)

    for (int j0g = 0; j0g < L_; j0g += FBN) {
        __syncthreads();            // prior tile's Ks/Vs reads complete
        {
            int r  = tid >> 2;
            int cb = (tid & 3) * 16;
#pragma unroll
            for (int c = 0; c < 16; c += 4) {
                float4 v4 = *reinterpret_cast<const float4*>(&Kb[(long)(j0g+r)*D_ + cb + c]);
                Ks[cb+c+0][r] = v4.x; Ks[cb+c+1][r] = v4.y;
                Ks[cb+c+2][r] = v4.z; Ks[cb+c+3][r] = v4.w;
                *reinterpret_cast<float4*>(&Vs[r][cb+c]) =
                    *reinterpret_cast<const float4*>(&Vb[(long)(j0g+r)*D_ + cb + c]);
            }
        }
        __syncthreads();

        // S tile: s[r][c] = sum_d Q[i0+r][d] * K[j0g+c0l+c][d]
        float s[4][4] = {};
#pragma unroll
        for (int kk = 0; kk < D_; kk++) {
            float4 a  = *reinterpret_cast<const float4*>(&Qs[kk][i0]);
            float4 bb = *reinterpret_cast<const float4*>(&Ks[kk][c0l]);
            const float av[4] = {a.x, a.y, a.z, a.w};
            const float bv[4] = {bb.x, bb.y, bb.z, bb.w};
#pragma unroll
            for (int r = 0; r < 4; r++)
#pragma unroll
                for (int c = 0; c < 4; c++)
                    s[r][c] = fmaf(av[r], bv[c], s[r][c]);
        }

        // Online softmax (row stats reduced across the 16-lane tx group)
        float mt[4], ps[4];
#pragma unroll
        for (int r = 0; r < 4; r++) {
            float m = s[r][0]*scale;
#pragma unroll
            for (int c = 1; c < 4; c++) m = fmaxf(m, s[r][c]*scale);
            mt[r] = m;
        }
#pragma unroll
        for (int o = 8; o; o >>= 1)
#pragma unroll
            for (int r = 0; r < 4; r++)
                mt[r] = fmaxf(mt[r], __shfl_xor_sync(0xffffffffu, mt[r], o, 16));

#pragma unroll
        for (int r = 0; r < 4; r++) {
            float mnew = fmaxf(m_i[r], mt[r]);
            float corr = __expf(m_i[r] - mnew);
            float sum = 0.f;
#pragma unroll
            for (int c = 0; c < 4; c++) {
                s[r][c] = __expf(s[r][c]*scale - mnew);
                sum += s[r][c];
            }
            ps[r] = sum;
            m_i[r] = mnew;
            l_i[r] *= corr;
#pragma unroll
            for (int c = 0; c < 4; c++) acc[r][c] *= corr;
        }
#pragma unroll
        for (int o = 8; o; o >>= 1)
#pragma unroll
            for (int r = 0; r < 4; r++)
                ps[r] += __shfl_xor_sync(0xffffffffu, ps[r], o, 16);
#pragma unroll
        for (int r = 0; r < 4; r++) l_i[r] += ps[r];

        // PV: acc[r][c] += sum_j P[r][j] * V[j][c0l+c]
        // P[r][j] lives in lane (j>>2) of this 16-lane row group, slot (j&3).
#pragma unroll
        for (int j = 0; j < FBN; j++) {
            const int src = j >> 2;    // compile-time after unroll
            float p[4];
#pragma unroll
            for (int r = 0; r < 4; r++)
                p[r] = __shfl_sync(0xffffffffu, s[r][j & 3], src, 16);
            float4 vv = *reinterpret_cast<const float4*>(&Vs[j][c0l]);
#pragma unroll
            for (int r = 0; r < 4; r++) {
                acc[r][0] = fmaf(p[r], vv.x, acc[r][0]);
                acc[r][1] = fmaf(p[r], vv.y, acc[r][1]);
                acc[r][2] = fmaf(p[r], vv.z, acc[r][2]);
                acc[r][3] = fmaf(p[r], vv.w, acc[r][3]);
            }
        }
    }

    // Normalize, write to g_o [B,L,E] at column h*64
#pragma unroll
    for (int r = 0; r < 4; r++) {
        float inv = 1.f / l_i[r];
        float4 v4 = make_float4(acc[r][0]*inv, acc[r][1]*inv,
                                acc[r][2]*inv, acc[r][3]*inv);
        *reinterpret_cast<float4*>(
            &g_o[((long)(b*L_ + i0g + i0 + r) * E_) + h*D_ + c0l]) = v4;
    }
}

// ---------------------------------------------------------------------------
// kernel_launch: kernel launches ONLY. No statics, no attribute calls,
// no symbol lookups — maximally graph-capture-safe.
// ---------------------------------------------------------------------------
extern "C" void kernel_launch(void* const* d_in, const int* in_sizes, int n_in,
                              void* d_out, int out_size)
{
    const float* hidden = (const float*)d_in[0];
    const float* Wq = (const float*)d_in[1];
    const float* bq = (const float*)d_in[2];
    const float* Wk = (const float*)d_in[3];
    const float* bk = (const float*)d_in[4];
    const float* Wv = (const float*)d_in[5];
    const float* bv = (const float*)d_in[6];
    const float* Wo = (const float*)d_in[7];
    const float* bo = (const float*)d_in[8];
    float* out = (float*)d_out;

    dim3 pgrid(E_/128, M_/128);
    // 1) Projections -> g_q, g_k, g_v (scatter to [B,H,L,D])
    gemm_nt<128,128,32,8,8,1><<<pgrid,256>>>(hidden, Wq, bq, nullptr, M_, E_, E_);
    gemm_nt<128,128,32,8,8,2><<<pgrid,256>>>(hidden, Wk, bk, nullptr, M_, E_, E_);
    gemm_nt<128,128,32,8,8,3><<<pgrid,256>>>(hidden, Wv, bv, nullptr, M_, E_, E_);

    // 2) Fused attention: g_q,g_k,g_v -> g_o [B,L,E]
    {
        dim3 grid(L_/FBM, B_*H_);
        flash_attn<<<grid, 256>>>();
    }

    // 3) Output projection: out = g_o @ Wo^T + bo
    gemm_nt<128,128,32,8,8,0><<<pgrid,256>>>(nullptr, Wo, bo, out, M_, E_, E_);
}

// round 4
// speedup vs baseline: 2.7541x; 2.7541x over previous
#include <cuda_runtime.h>
#include <cstdint>

#define B_ 2
#define L_ 2048
#define E_ 1024
#define H_ 16
#define D_ 64
#define M_ (B_*L_)   // 4096

// Scratch (allocation-free rule: __device__ globals). 64 MB total.
__device__ float g_q[B_*H_*L_*D_];   // [B,H,L,D]
__device__ float g_k[B_*H_*L_*D_];   // [B,H,L,D]
__device__ float g_v[B_*H_*L_*D_];   // [B,H,L,D]
__device__ float g_o[B_*L_*E_];      // [B,L,E]

// ---------------------------------------------------------------------------
// Helpers: tf32 convert (round-to-nearest; avoids truncation bias), exp2,
// and the m16n8k8 tf32 tensor-core MMA (D += A*B, fp32 accumulate).
// Fragment layout (PTX, lane = 4*g + t, g=lane>>2, t=lane&3):
//   A(16x8 row): a0=(g,t) a1=(g+8,t) a2=(g,t+4) a3=(g+8,t+4)
//   B(8x8 col):  b0=(t,g) b1=(t+4,g)
//   C(16x8):     c0=(g,2t) c1=(g,2t+1) c2=(g+8,2t) c3=(g+8,2t+1)
// ---------------------------------------------------------------------------
__device__ __forceinline__ uint32_t f2tf(float x) {
    uint32_t r; asm("cvt.rna.tf32.f32 %0, %1;" : "=r"(r) : "f"(x)); return r;
}
__device__ __forceinline__ float ex2(float x) {
    float r; asm("ex2.approx.f32 %0, %1;" : "=f"(r) : "f"(x)); return r;
}
__device__ __forceinline__ void mma8(float* d, const uint32_t* a, const uint32_t* b) {
    asm("mma.sync.aligned.m16n8k8.row.col.f32.tf32.tf32.f32 "
        "{%0,%1,%2,%3},{%4,%5,%6,%7},{%8,%9},{%0,%1,%2,%3};"
        : "+f"(d[0]), "+f"(d[1]), "+f"(d[2]), "+f"(d[3])
        : "r"(a[0]), "r"(a[1]), "r"(a[2]), "r"(a[3]), "r"(b[0]), "r"(b[1]));
}

// ---------------------------------------------------------------------------
// TF32 NT GEMM:  C = A(MxK) @ W(NxK)^T + bias,  M=4096, N=K=1024.
// Block 256 thr (8 warps, 2x4), tile 128x128x32, warp tile 64x32.
// Smem stride 136: fragment-read bank = (8t+g)%32 -> conflict-free.
// MODE 0: A = g_o, C row-major [M,N]   (output projection)
// MODE 1/2/3: C = g_q/g_k/g_v scatter [B,H,L,D]   (input projections)
// ---------------------------------------------------------------------------
template<int MODE>
__global__ void __launch_bounds__(256)
gemm_tf32(const float* __restrict__ Ap, const float* __restrict__ W,
          const float* __restrict__ bias, float* __restrict__ Cp)
{
    __shared__ uint32_t As[32][136];
    __shared__ uint32_t Bs[32][136];

    const float* A = (MODE == 0) ? (const float*)g_o : Ap;
    float* C = (MODE == 0) ? Cp
             : (MODE == 1) ? (float*)g_q
             : (MODE == 2) ? (float*)g_k
             :               (float*)g_v;

    const int m0 = blockIdx.y * 128, n0 = blockIdx.x * 128;
    const int tid = threadIdx.x, lane = tid & 31, wid = tid >> 5;
    const int g = lane >> 2, t = lane & 3;
    const int wm = (wid >> 2) * 64, wn = (wid & 3) * 32;

    float acc[4][4][4] = {};

    const int r  = tid >> 1;          // staging row 0..127
    const int ch = (tid & 1) * 16;    // staging col half

    for (int k0 = 0; k0 < E_; k0 += 32) {
        const float* Arow = A + (long)(m0 + r) * E_ + k0 + ch;
        const float* Wrow = W + (long)(n0 + r) * E_ + k0 + ch;
#pragma unroll
        for (int u = 0; u < 4; u++) {
            float4 a4 = *(const float4*)(Arow + 4*u);
            float4 b4 = *(const float4*)(Wrow + 4*u);
            As[ch+4*u+0][r] = f2tf(a4.x); As[ch+4*u+1][r] = f2tf(a4.y);
            As[ch+4*u+2][r] = f2tf(a4.z); As[ch+4*u+3][r] = f2tf(a4.w);
            Bs[ch+4*u+0][r] = f2tf(b4.x); Bs[ch+4*u+1][r] = f2tf(b4.y);
            Bs[ch+4*u+2][r] = f2tf(b4.z); Bs[ch+4*u+3][r] = f2tf(b4.w);
        }
        __syncthreads();

#pragma unroll
        for (int ks = 0; ks < 4; ks++) {
            const int kk = ks * 8;
            uint32_t af[4][4], bf[4][2];
#pragma unroll
            for (int mt = 0; mt < 4; mt++) {
                const int mb = wm + mt*16;
                af[mt][0] = As[kk+t  ][mb+g  ];
                af[mt][1] = As[kk+t  ][mb+g+8];
                af[mt][2] = As[kk+t+4][mb+g  ];
                af[mt][3] = As[kk+t+4][mb+g+8];
            }
#pragma unroll
            for (int nt = 0; nt < 4; nt++) {
                const int nb = wn + nt*8;
                bf[nt][0] = Bs[kk+t  ][nb+g];
                bf[nt][1] = Bs[kk+t+4][nb+g];
            }
#pragma unroll
            for (int mt = 0; mt < 4; mt++)
#pragma unroll
                for (int nt = 0; nt < 4; nt++)
                    mma8(acc[mt][nt], af[mt], bf[nt]);
        }
        __syncthreads();
    }

    // Epilogue
#pragma unroll
    for (int mt = 0; mt < 4; mt++) {
        const int row = m0 + wm + mt*16 + g;
#pragma unroll
        for (int nt = 0; nt < 4; nt++) {
            const int col = n0 + wn + nt*8 + 2*t;
            const float b0 = bias ? bias[col]   : 0.f;
            const float b1 = bias ? bias[col+1] : 0.f;
            float v00 = acc[mt][nt][0] + b0, v01 = acc[mt][nt][1] + b1;
            float v10 = acc[mt][nt][2] + b0, v11 = acc[mt][nt][3] + b1;
            if (MODE == 0) {
                *(float2*)&C[(long)row * E_ + col]     = make_float2(v00, v01);
                *(float2*)&C[(long)(row+8) * E_ + col] = make_float2(v10, v11);
            } else {
                const int h = col >> 6, d = col & 63;
                const int b  = row >> 11, l = row & (L_-1);
                long base = (((long)(b*H_ + h) * L_ + l) * D_) + d;
                *(float2*)&C[base]          = make_float2(v00, v01);
                *(float2*)&C[base + 8*D_]   = make_float2(v10, v11);  // l+8
            }
        }
    }
}

// ---------------------------------------------------------------------------
// Flash attention, tf32 tensor cores.  Block 256 thr = 8 warps; each warp
// owns 16 q-rows (block: 128 q-rows of one (b,h)); KV tiles of 64.
// Q lives in A-fragments (registers).  K,V staged tf32 in smem with pads
// chosen so fragment reads are bank-conflict-free (Ks stride 68: (4g+t)%32;
// Vs stride 72: (8t+g)%32).  P is passed S-frag -> A-frag via quad shuffles.
// Q pre-scaled by scale*log2e so softmax is pure ex2.
// ---------------------------------------------------------------------------
__global__ void __launch_bounds__(256)
flash_tf32()
{
    __shared__ uint32_t Ks[64][68];
    __shared__ uint32_t Vs[64][72];

    const int bh = blockIdx.y, b = bh >> 4, h = bh & 15;
    const int i0g = blockIdx.x * 128;
    const int tid = threadIdx.x, lane = tid & 31, w = tid >> 5;
    const int g = lane >> 2, t = lane & 3;
    const int qw = i0g + w * 16;

    const float* Qb = g_q + (long)bh * L_ * D_;
    const float* Kb = g_k + (long)bh * L_ * D_;
    const float* Vb = g_v + (long)bh * L_ * D_;

    const float qscale = 0.125f * 1.4426950408889634f;   // scale * log2(e)

    // Q fragments: 8 k-chunks x 4 regs, held for the whole kernel
    uint32_t qa[8][4];
#pragma unroll
    for (int kc = 0; kc < 8; kc++) {
        const long r0 = (long)(qw + g) * D_ + kc*8;
        const long r1 = (long)(qw + g + 8) * D_ + kc*8;
        qa[kc][0] = f2tf(qscale * Qb[r0 + t]);
        qa[kc][1] = f2tf(qscale * Qb[r1 + t]);
        qa[kc][2] = f2tf(qscale * Qb[r0 + t + 4]);
        qa[kc][3] = f2tf(qscale * Qb[r1 + t + 4]);
    }

    float oa[8][4] = {};
    float m0v = -1e30f, m1v = -1e30f, l0 = 0.f, l1 = 0.f;

    const int sr = tid >> 2;            // staging row 0..63
    const int sc = (tid & 3) * 16;      // staging col seg

    for (int j0 = 0; j0 < L_; j0 += 64) {
        __syncthreads();
        {
            const float* Kr = Kb + (long)(j0 + sr) * D_ + sc;
            const float* Vr = Vb + (long)(j0 + sr) * D_ + sc;
#pragma unroll
            for (int u = 0; u < 4; u++) {
                float4 k4 = *(const float4*)(Kr + 4*u);
                float4 v4 = *(const float4*)(Vr + 4*u);
                Ks[sr][sc+4*u+0] = f2tf(k4.x); Ks[sr][sc+4*u+1] = f2tf(k4.y);
                Ks[sr][sc+4*u+2] = f2tf(k4.z); Ks[sr][sc+4*u+3] = f2tf(k4.w);
                Vs[sr][sc+4*u+0] = f2tf(v4.x); Vs[sr][sc+4*u+1] = f2tf(v4.y);
                Vs[sr][sc+4*u+2] = f2tf(v4.z); Vs[sr][sc+4*u+3] = f2tf(v4.w);
            }
        }
        __syncthreads();

        // S = Q @ K^T  (8 n-tiles of 8 keys x 8 k-chunks over D=64)
        float sf[8][4] = {};
#pragma unroll
        for (int jn = 0; jn < 8; jn++) {
#pragma unroll
            for (int kc = 0; kc < 8; kc++) {
                uint32_t bb[2] = { Ks[jn*8 + g][kc*8 + t],
                                   Ks[jn*8 + g][kc*8 + t + 4] };
                mma8(sf[jn], qa[kc], bb);
            }
        }

        // Online softmax (row stats fully within each quad)
        float mx0 = -1e30f, mx1 = -1e30f;
#pragma unroll
        for (int jn = 0; jn < 8; jn++) {
            mx0 = fmaxf(mx0, fmaxf(sf[jn][0], sf[jn][1]));
            mx1 = fmaxf(mx1, fmaxf(sf[jn][2], sf[jn][3]));
        }
        mx0 = fmaxf(mx0, __shfl_xor_sync(0xffffffffu, mx0, 1));
        mx0 = fmaxf(mx0, __shfl_xor_sync(0xffffffffu, mx0, 2));
        mx1 = fmaxf(mx1, __shfl_xor_sync(0xffffffffu, mx1, 1));
        mx1 = fmaxf(mx1, __shfl_xor_sync(0xffffffffu, mx1, 2));

        const float mn0 = fmaxf(m0v, mx0), mn1 = fmaxf(m1v, mx1);
        const float c0 = ex2(m0v - mn0),   c1 = ex2(m1v - mn1);
        m0v = mn0; m1v = mn1;

        float s0 = 0.f, s1 = 0.f;
        uint32_t pu[8][4];
#pragma unroll
        for (int jn = 0; jn < 8; jn++) {
            float p0 = ex2(sf[jn][0] - mn0);
            float p1 = ex2(sf[jn][1] - mn0);
            float p2 = ex2(sf[jn][2] - mn1);
            float p3 = ex2(sf[jn][3] - mn1);
            s0 += p0 + p1;  s1 += p2 + p3;
            pu[jn][0] = f2tf(p0); pu[jn][1] = f2tf(p1);
            pu[jn][2] = f2tf(p2); pu[jn][3] = f2tf(p3);
        }
        s0 += __shfl_xor_sync(0xffffffffu, s0, 1);
        s0 += __shfl_xor_sync(0xffffffffu, s0, 2);
        s1 += __shfl_xor_sync(0xffffffffu, s1, 1);
        s1 += __shfl_xor_sync(0xffffffffu, s1, 2);
        l0 = l0 * c0 + s0;
        l1 = l1 * c1 + s1;

#pragma unroll
        for (int dn = 0; dn < 8; dn++) {
            oa[dn][0] *= c0; oa[dn][1] *= c0;
            oa[dn][2] *= c1; oa[dn][3] *= c1;
        }

        // PV: gather P A-fragments from S-fragments via quad shuffles
        const int base = lane & ~3;
        const int sl1 = base | (t >> 1);
        const int sl2 = base | ((t >> 1) + 2);
        const bool odd = (t & 1);
#pragma unroll
        for (int kc = 0; kc < 8; kc++) {
            uint32_t v00 = __shfl_sync(0xffffffffu, pu[kc][0], sl1);
            uint32_t v01 = __shfl_sync(0xffffffffu, pu[kc][1], sl1);
            uint32_t v02 = __shfl_sync(0xffffffffu, pu[kc][2], sl1);
            uint32_t v03 = __shfl_sync(0xffffffffu, pu[kc][3], sl1);
            uint32_t v10 = __shfl_sync(0xffffffffu, pu[kc][0], sl2);
            uint32_t v11 = __shfl_sync(0xffffffffu, pu[kc][1], sl2);
            uint32_t v12 = __shfl_sync(0xffffffffu, pu[kc][2], sl2);
            uint32_t v13 = __shfl_sync(0xffffffffu, pu[kc][3], sl2);
            uint32_t af[4];
            af[0] = odd ? v01 : v00;   // P[g   ][j0+t]
            af[1] = odd ? v03 : v02;   // P[g+8 ][j0+t]
            af[2] = odd ? v11 : v10;   // P[g   ][j0+t+4]
            af[3] = odd ? v13 : v12;   // P[g+8 ][j0+t+4]
#pragma unroll
            for (int dn = 0; dn < 8; dn++) {
                uint32_t bb[2] = { Vs[kc*8 + t    ][dn*8 + g],
                                   Vs[kc*8 + t + 4][dn*8 + g] };
                mma8(oa[dn], af, bb);
            }
        }
    }

    // Normalize and write to g_o [B,L,E] at column h*64
    const float inv0 = 1.f / l0, inv1 = 1.f / l1;
    const long ro0 = (long)(b*L_ + qw + g)     * E_ + h*D_;
    const long ro1 = (long)(b*L_ + qw + g + 8) * E_ + h*D_;
#pragma unroll
    for (int dn = 0; dn < 8; dn++) {
        const int col = dn*8 + 2*t;
        *(float2*)&g_o[ro0 + col] = make_float2(oa[dn][0]*inv0, oa[dn][1]*inv0);
        *(float2*)&g_o[ro1 + col] = make_float2(oa[dn][2]*inv1, oa[dn][3]*inv1);
    }
}

// ---------------------------------------------------------------------------
extern "C" void kernel_launch(void* const* d_in, const int* in_sizes, int n_in,
                              void* d_out, int out_size)
{
    const float* hidden = (const float*)d_in[0];
    const float* Wq = (const float*)d_in[1];
    const float* bq = (const float*)d_in[2];
    const float* Wk = (const float*)d_in[3];
    const float* bk = (const float*)d_in[4];
    const float* Wv = (const float*)d_in[5];
    const float* bv = (const float*)d_in[6];
    const float* Wo = (const float*)d_in[7];
    const float* bo = (const float*)d_in[8];
    float* out = (float*)d_out;

    dim3 pgrid(E_/128, M_/128);   // (8, 32)
    gemm_tf32<1><<<pgrid, 256>>>(hidden, Wq, bq, nullptr);
    gemm_tf32<2><<<pgrid, 256>>>(hidden, Wk, bk, nullptr);
    gemm_tf32<3><<<pgrid, 256>>>(hidden, Wv, bv, nullptr);

    dim3 fgrid(L_/128, B_*H_);    // (16, 32)
    flash_tf32<<<fgrid, 256>>>();

    gemm_tf32<0><<<pgrid, 256>>>(nullptr, Wo, bo, out);
}

// round 5
// speedup vs baseline: 3.4302x; 1.2455x over previous
#include <cuda_runtime.h>
#include <cstdint>

#define B_ 2
#define L_ 2048
#define E_ 1024
#define H_ 16
#define D_ 64
#define M_ (B_*L_)   // 4096

// Scratch (__device__ globals; ~64 MB total)
__device__ float g_x [M_*E_];          // tf32(hidden)
__device__ float g_w [4*E_*E_];        // tf32 weights: Wq,Wk,Wv,Wo
__device__ float g_q [B_*H_*L_*D_];    // tf32(qscale*Q), [B,H,L,D]
__device__ float g_k [B_*H_*L_*D_];    // tf32 K, [B,H,L,dperm]
__device__ float g_vT[B_*H_*D_*L_];    // tf32 V^T, [B,H,D,jperm]
__device__ float g_o [B_*L_*E_];       // tf32 attention out, [B,L,E]

// ---------------------------------------------------------------------------
__device__ __forceinline__ uint32_t f2tf(float x) {
    uint32_t r; asm("cvt.rna.tf32.f32 %0, %1;" : "=r"(r) : "f"(x)); return r;
}
__device__ __forceinline__ float tfb(float x) {   // tf32 bits as float
    return __uint_as_float(f2tf(x));
}
__device__ __forceinline__ float ex2(float x) {
    float r; asm("ex2.approx.f32 %0, %1;" : "=f"(r) : "f"(x)); return r;
}
__device__ __forceinline__ void mma8(float* d, const uint32_t* a, const uint32_t* b) {
    asm("mma.sync.aligned.m16n8k8.row.col.f32.tf32.tf32.f32 "
        "{%0,%1,%2,%3},{%4,%5,%6,%7},{%8,%9},{%0,%1,%2,%3};"
        : "+f"(d[0]), "+f"(d[1]), "+f"(d[2]), "+f"(d[3])
        : "r"(a[0]), "r"(a[1]), "r"(a[2]), "r"(a[3]), "r"(b[0]), "r"(b[1]));
}
__device__ __forceinline__ void cp16(void* dst, const void* src) {
    uint32_t d = (uint32_t)__cvta_generic_to_shared(dst);
    asm volatile("cp.async.cg.shared.global [%0], [%1], 16;" :: "r"(d), "l"(src));
}
__device__ __forceinline__ void cp_commit() {
    asm volatile("cp.async.commit_group;");
}
__device__ __forceinline__ void cp_wait0() {
    asm volatile("cp.async.wait_group 0;" ::: "memory");
}

#define QSCALE 0.18033688011112042f   // 0.125 * log2(e)

// ---------------------------------------------------------------------------
// Pre-pass: convert inputs to tf32 bit patterns (round-to-nearest).
// ---------------------------------------------------------------------------
__global__ void cvt_x(const float4* __restrict__ src) {
    int i = blockIdx.x * 256 + threadIdx.x;        // 1M float4
    float4 v = src[i];
    ((float4*)g_x)[i] = make_float4(tfb(v.x), tfb(v.y), tfb(v.z), tfb(v.w));
}
__global__ void cvt_w(const float4* __restrict__ wq, const float4* __restrict__ wk,
                      const float4* __restrict__ wv, const float4* __restrict__ wo) {
    int z = blockIdx.z;
    int i = blockIdx.x * 256 + threadIdx.x;        // 256K float4 per z
    const float4* s = (z==0) ? wq : (z==1) ? wk : (z==2) ? wv : wo;
    float4 v = s[i];
    ((float4*)(g_w + (size_t)z * E_*E_))[i] =
        make_float4(tfb(v.x), tfb(v.y), tfb(v.z), tfb(v.w));
}

// ---------------------------------------------------------------------------
// Pipelined tf32 NT GEMM: C = A(4096x1024) @ W(1024x1024)^T + bias.
// cp.async double-buffered, BK=32, block 256 (8 warps, 64x32 warp tiles).
// Smem [128][36] per operand per stage: fragment reads conflict-free.
// ISQKV=1: z=blockIdx.z selects Wq/Wk/Wv; epilogue scatters Q (pre-scaled
//          tf32), K (d-permuted tf32), V^T (j-permuted tf32).
// ISQKV=0: A=g_o, W=Wo; epilogue writes final f32 output.
// ---------------------------------------------------------------------------
#define GSMEM (2*2*128*36*4)   // 73728 B

template<int ISQKV>
__global__ void __launch_bounds__(256, 2)
gemm_pipe(const float* __restrict__ b0p, const float* __restrict__ b1p,
          const float* __restrict__ b2p, float* __restrict__ outp)
{
    extern __shared__ uint32_t smg[];
    uint32_t (*As)[128][36] = (uint32_t(*)[128][36])smg;
    uint32_t (*Bs)[128][36] = (uint32_t(*)[128][36])(smg + 2*128*36);

    const int z = ISQKV ? blockIdx.z : 3;
    const float* A = ISQKV ? g_x : g_o;
    const float* W = g_w + (size_t)z * E_*E_;
    const float* bias = ISQKV ? ((z==0) ? b0p : (z==1) ? b1p : b2p) : b0p;

    const int m0 = blockIdx.y * 128, n0 = blockIdx.x * 128;
    const int tid = threadIdx.x, lane = tid & 31, wid = tid >> 5;
    const int g = lane >> 2, t = lane & 3;
    const int wm = (wid >> 2) * 64, wn = (wid & 3) * 32;

    const int mr = tid >> 1, sg = (tid & 1) * 16;
    const float* Asrc = A + (long)(m0 + mr) * E_ + sg;
    const float* Wsrc = W + (long)(n0 + mr) * E_ + sg;

    float acc[4][4][4] = {};

    // prologue: stage 0
#pragma unroll
    for (int u = 0; u < 4; u++) {
        cp16(&As[0][mr][sg + 4*u], Asrc + 4*u);
        cp16(&Bs[0][mr][sg + 4*u], Wsrc + 4*u);
    }
    cp_commit();

    for (int s = 0; s < 32; s++) {
        cp_wait0();
        __syncthreads();
        if (s < 31) {
            const float* a2 = Asrc + (s+1)*32;
            const float* w2 = Wsrc + (s+1)*32;
            const int nb = (s+1) & 1;
#pragma unroll
            for (int u = 0; u < 4; u++) {
                cp16(&As[nb][mr][sg + 4*u], a2 + 4*u);
                cp16(&Bs[nb][mr][sg + 4*u], w2 + 4*u);
            }
            cp_commit();
        }
        const int bu = s & 1;
#pragma unroll
        for (int ks = 0; ks < 4; ks++) {
            const int kk = ks * 8;
            uint32_t af[4][4], bf[4][2];
#pragma unroll
            for (int mt = 0; mt < 4; mt++) {
                const int mb = wm + mt*16;
                af[mt][0] = As[bu][mb+g  ][kk+t];
                af[mt][1] = As[bu][mb+g+8][kk+t];
                af[mt][2] = As[bu][mb+g  ][kk+t+4];
                af[mt][3] = As[bu][mb+g+8][kk+t+4];
            }
#pragma unroll
            for (int nt = 0; nt < 4; nt++) {
                bf[nt][0] = Bs[bu][wn+nt*8+g][kk+t];
                bf[nt][1] = Bs[bu][wn+nt*8+g][kk+t+4];
            }
#pragma unroll
            for (int mt = 0; mt < 4; mt++)
#pragma unroll
                for (int nt = 0; nt < 4; nt++)
                    mma8(acc[mt][nt], af[mt], bf[nt]);
        }
    }

    // Epilogue
#pragma unroll
    for (int mt = 0; mt < 4; mt++) {
        const int row = m0 + wm + mt*16 + g;
        const int b = row >> 11, l = row & (L_-1);
#pragma unroll
        for (int nt = 0; nt < 4; nt++) {
            const int col = n0 + wn + nt*8 + 2*t;
            const float bb0 = bias[col], bb1 = bias[col+1];
            float v00 = acc[mt][nt][0] + bb0, v01 = acc[mt][nt][1] + bb1;
            float v10 = acc[mt][nt][2] + bb0, v11 = acc[mt][nt][3] + bb1;
            if (!ISQKV) {
                *(float2*)&outp[(long)row * E_ + col]     = make_float2(v00, v01);
                *(float2*)&outp[(long)(row+8) * E_ + col] = make_float2(v10, v11);
            } else {
                const int h = col >> 6, d = col & 63;
                const long bh = b*H_ + h;
                if (z == 0) {            // Q: pre-scaled tf32, natural layout
                    long qb = (bh * L_ + l) * D_ + d;
                    *(float2*)&g_q[qb] =
                        make_float2(tfb(QSCALE*v00), tfb(QSCALE*v01));
                    *(float2*)&g_q[qb + 8*D_] =
                        make_float2(tfb(QSCALE*v10), tfb(QSCALE*v11));
                } else if (z == 1) {     // K: d-permuted tf32
                    long rb = (bh * L_ + l) * D_;
                    int dp0 = (d & 56) + 2*(d&3) + ((d>>2)&1);
                    int d1 = d + 1;
                    int dp1 = (d1 & 56) + 2*(d1&3) + ((d1>>2)&1);
                    g_k[rb + dp0]        = tfb(v00);
                    g_k[rb + dp1]        = tfb(v01);
                    g_k[rb + 8*D_ + dp0] = tfb(v10);
                    g_k[rb + 8*D_ + dp1] = tfb(v11);
                } else {                  // V: transposed, j-permuted tf32
                    long vb = (bh * D_ + d) * L_;
                    int jp = (l & ~7) + 2*(l&3) + ((l>>2)&1);
                    g_vT[vb + jp]            = tfb(v00);
                    g_vT[vb + L_ + jp]       = tfb(v01);
                    g_vT[vb + jp + 8]        = tfb(v10);
                    g_vT[vb + L_ + jp + 8]   = tfb(v11);
                }
            }
        }
    }
}

// ---------------------------------------------------------------------------
// Flash attention, tf32 tensor cores, cp.async double-buffered KV tiles.
// Block 256 (8 warps x 16 q-rows = 128 rows per (b,h) block); KV tiles of 64.
// K tile [j][dperm] / V^T tile [d][jperm], both stride 72: all MMA B-fragment
// reads are conflict-free LDS.64 pairs. Q pre-scaled+tf32 in registers.
// ---------------------------------------------------------------------------
#define FSMEM (2*2*64*72*4)    // 73728 B

__global__ void __launch_bounds__(256, 2)
flash_tf32()
{
    extern __shared__ uint32_t smf[];
    uint32_t (*Ks)[64][72] = (uint32_t(*)[64][72])smf;            // [2]
    uint32_t (*Vs)[64][72] = (uint32_t(*)[64][72])(smf + 2*64*72);

    const int bh = blockIdx.y, b = bh >> 4, h = bh & 15;
    const int i0g = blockIdx.x * 128;
    const int tid = threadIdx.x, lane = tid & 31, w = tid >> 5;
    const int g = lane >> 2, t = lane & 3;
    const int qw = i0g + w * 16;

    const float* Qb = g_q + (long)bh * L_ * D_;
    const float* Kb = g_k + (long)bh * L_ * D_;
    const float* Vb = g_vT + (long)bh * D_ * L_;

    // Q fragments (bits already tf32, pre-scaled)
    uint32_t qa[8][4];
#pragma unroll
    for (int kc = 0; kc < 8; kc++) {
        qa[kc][0] = __float_as_uint(Qb[(long)(qw+g)  *D_ + kc*8+t]);
        qa[kc][1] = __float_as_uint(Qb[(long)(qw+g+8)*D_ + kc*8+t]);
        qa[kc][2] = __float_as_uint(Qb[(long)(qw+g)  *D_ + kc*8+t+4]);
        qa[kc][3] = __float_as_uint(Qb[(long)(qw+g+8)*D_ + kc*8+t+4]);
    }

    float oa[8][4] = {};
    float m0v = -1e30f, m1v = -1e30f, l0 = 0.f, l1 = 0.f;

    const int sr = tid >> 2;          // copy row 0..63
    const int cc = tid & 3;           // chunk lane

    // prologue: tile 0 -> buf 0
    {
        const float* ksrc = Kb + (long)sr * D_;
        const float* vsrc = Vb + (long)sr * L_;
#pragma unroll
        for (int u = 0; u < 4; u++) {
            int c4 = (cc + 4*u) * 4;
            cp16(&Ks[0][sr][c4], ksrc + c4);
            cp16(&Vs[0][sr][c4], vsrc + c4);
        }
        cp_commit();
    }

    for (int tt = 0; tt < 32; tt++) {
        cp_wait0();
        __syncthreads();
        if (tt < 31) {
            const int j1 = (tt+1) * 64, nb = (tt+1) & 1;
            const float* ksrc = Kb + (long)(j1 + sr) * D_;
            const float* vsrc = Vb + (long)sr * L_ + j1;
#pragma unroll
            for (int u = 0; u < 4; u++) {
                int c4 = (cc + 4*u) * 4;
                cp16(&Ks[nb][sr][c4], ksrc + c4);
                cp16(&Vs[nb][sr][c4], vsrc + c4);
            }
            cp_commit();
        }
        const int bu = tt & 1;

        // S = Q @ K^T : B-fragments as LDS.64 pairs (orig d = t, t+4)
        float sf[8][4] = {};
#pragma unroll
        for (int jn = 0; jn < 8; jn++) {
#pragma unroll
            for (int kc = 0; kc < 8; kc++) {
                uint2 bb = *(const uint2*)&Ks[bu][jn*8+g][kc*8 + 2*t];
                mma8(sf[jn], qa[kc], &bb.x);
            }
        }

        // Online softmax (log2 domain; stats within each quad)
        float mx0 = -1e30f, mx1 = -1e30f;
#pragma unroll
        for (int jn = 0; jn < 8; jn++) {
            mx0 = fmaxf(mx0, fmaxf(sf[jn][0], sf[jn][1]));
            mx1 = fmaxf(mx1, fmaxf(sf[jn][2], sf[jn][3]));
        }
        mx0 = fmaxf(mx0, __shfl_xor_sync(0xffffffffu, mx0, 1));
        mx0 = fmaxf(mx0, __shfl_xor_sync(0xffffffffu, mx0, 2));
        mx1 = fmaxf(mx1, __shfl_xor_sync(0xffffffffu, mx1, 1));
        mx1 = fmaxf(mx1, __shfl_xor_sync(0xffffffffu, mx1, 2));

        const float mn0 = fmaxf(m0v, mx0), mn1 = fmaxf(m1v, mx1);
        const float c0 = ex2(m0v - mn0),   c1 = ex2(m1v - mn1);
        m0v = mn0; m1v = mn1;

        float s0 = 0.f, s1 = 0.f;
        uint32_t pu[8][4];
#pragma unroll
        for (int jn = 0; jn < 8; jn++) {
            float p0 = ex2(sf[jn][0] - mn0);
            float p1 = ex2(sf[jn][1] - mn0);
            float p2 = ex2(sf[jn][2] - mn1);
            float p3 = ex2(sf[jn][3] - mn1);
            s0 += p0 + p1;  s1 += p2 + p3;
            pu[jn][0] = f2tf(p0); pu[jn][1] = f2tf(p1);
            pu[jn][2] = f2tf(p2); pu[jn][3] = f2tf(p3);
        }
        s0 += __shfl_xor_sync(0xffffffffu, s0, 1);
        s0 += __shfl_xor_sync(0xffffffffu, s0, 2);
        s1 += __shfl_xor_sync(0xffffffffu, s1, 1);
        s1 += __shfl_xor_sync(0xffffffffu, s1, 2);
        l0 = l0 * c0 + s0;
        l1 = l1 * c1 + s1;

#pragma unroll
        for (int dn = 0; dn < 8; dn++) {
            oa[dn][0] *= c0; oa[dn][1] *= c0;
            oa[dn][2] *= c1; oa[dn][3] *= c1;
        }

        // PV: P A-fragments from S-fragments via quad shuffles;
        // V B-fragments as LDS.64 pairs (orig j = t, t+4)
        const int base = lane & ~3;
        const int sl1 = base | (t >> 1);
        const int sl2 = base | ((t >> 1) + 2);
        const bool odd = (t & 1);
#pragma unroll
        for (int kc = 0; kc < 8; kc++) {
            uint32_t v00 = __shfl_sync(0xffffffffu, pu[kc][0], sl1);
            uint32_t v01 = __shfl_sync(0xffffffffu, pu[kc][1], sl1);
            uint32_t v02 = __shfl_sync(0xffffffffu, pu[kc][2], sl1);
            uint32_t v03 = __shfl_sync(0xffffffffu, pu[kc][3], sl1);
            uint32_t v10 = __shfl_sync(0xffffffffu, pu[kc][0], sl2);
            uint32_t v11 = __shfl_sync(0xffffffffu, pu[kc][1], sl2);
            uint32_t v12 = __shfl_sync(0xffffffffu, pu[kc][2], sl2);
            uint32_t v13 = __shfl_sync(0xffffffffu, pu[kc][3], sl2);
            uint32_t af[4];
            af[0] = odd ? v01 : v00;
            af[1] = odd ? v03 : v02;
            af[2] = odd ? v11 : v10;
            af[3] = odd ? v13 : v12;
#pragma unroll
            for (int dn = 0; dn < 8; dn++) {
                uint2 bb = *(const uint2*)&Vs[bu][dn*8+g][kc*8 + 2*t];
                mma8(oa[dn], af, &bb.x);
            }
        }
    }

    // Normalize; store tf32-rounded so the output GEMM can cp.async directly
    const float inv0 = 1.f / l0, inv1 = 1.f / l1;
    const long ro0 = (long)(b*L_ + qw + g)     * E_ + h*D_;
    const long ro1 = (long)(b*L_ + qw + g + 8) * E_ + h*D_;
#pragma unroll
    for (int dn = 0; dn < 8; dn++) {
        const int col = dn*8 + 2*t;
        *(float2*)&g_o[ro0 + col] =
            make_float2(tfb(oa[dn][0]*inv0), tfb(oa[dn][1]*inv0));
        *(float2*)&g_o[ro1 + col] =
            make_float2(tfb(oa[dn][2]*inv1), tfb(oa[dn][3]*inv1));
    }
}

// ---------------------------------------------------------------------------
extern "C" void kernel_launch(void* const* d_in, const int* in_sizes, int n_in,
                              void* d_out, int out_size)
{
    const float* hidden = (const float*)d_in[0];
    const float* Wq = (const float*)d_in[1];
    const float* bq = (const float*)d_in[2];
    const float* Wk = (const float*)d_in[3];
    const float* bk = (const float*)d_in[4];
    const float* Wv = (const float*)d_in[5];
    const float* bv = (const float*)d_in[6];
    const float* Wo = (const float*)d_in[7];
    const float* bo = (const float*)d_in[8];
    float* out = (float*)d_out;

    cudaFuncSetAttribute(gemm_pipe<1>, cudaFuncAttributeMaxDynamicSharedMemorySize, GSMEM);
    cudaFuncSetAttribute(gemm_pipe<0>, cudaFuncAttributeMaxDynamicSharedMemorySize, GSMEM);
    cudaFuncSetAttribute(flash_tf32,   cudaFuncAttributeMaxDynamicSharedMemorySize, FSMEM);

    // 0) Pre-convert inputs to tf32 bit patterns
    cvt_x<<<M_*E_/4/256, 256>>>((const float4*)hidden);
    cvt_w<<<dim3(E_*E_/4/256, 1, 4), 256>>>((const float4*)Wq, (const float4*)Wk,
                                            (const float4*)Wv, (const float4*)Wo);

    // 1) Fused QKV projections (z = 0,1,2)
    gemm_pipe<1><<<dim3(E_/128, M_/128, 3), 256, GSMEM>>>(bq, bk, bv, nullptr);

    // 2) Flash attention
    flash_tf32<<<dim3(L_/128, B_*H_), 256, FSMEM>>>();

    // 3) Output projection
    gemm_pipe<0><<<dim3(E_/128, M_/128, 1), 256, GSMEM>>>(bo, nullptr, nullptr, out);
}

// round 7
// speedup vs baseline: 3.4735x; 1.0126x over previous
#include <cuda_runtime.h>
#include <cstdint>

#define B_ 2
#define L_ 2048
#define E_ 1024
#define H_ 16
#define D_ 64
#define M_ (B_*L_)   // 4096

// Scratch (__device__ globals)
__device__ float g_x [M_*E_];          // tf32(hidden), k-pair-permuted cols
__device__ float g_w [4*E_*E_];        // tf32 weights, k-pair-permuted cols
__device__ float g_q [B_*H_*L_*D_];    // tf32(qscale*Q), [B,H,L,D] natural
__device__ float g_k [B_*H_*L_*D_];    // tf32 K, [B,H,L,dperm]
__device__ float g_vT[B_*H_*D_*L_];    // tf32 V^T, [B,H,D,jperm]
__device__ float g_o [B_*L_*E_];       // tf32 attn out, [B,L,E] k-pair-permuted

#define QSCALE 0.18033688011112042f    // 0.125 * log2(e)

// k-pair perm within 8-groups: k -> (k&~7) + 2*(k&3) + ((k>>2)&1)
__device__ __forceinline__ int kperm(int c) {
    return (c & ~7) + 2*(c & 3) + ((c >> 2) & 1);
}

// ---------------------------------------------------------------------------
__device__ __forceinline__ uint32_t f2tf(float x) {
    uint32_t r; asm("cvt.rna.tf32.f32 %0, %1;" : "=r"(r) : "f"(x)); return r;
}
__device__ __forceinline__ float tfb(float x) { return __uint_as_float(f2tf(x)); }
__device__ __forceinline__ float ex2(float x) {
    float r; asm("ex2.approx.f32 %0, %1;" : "=f"(r) : "f"(x)); return r;
}
__device__ __forceinline__ void mma8(float* d, const uint32_t* a, const uint32_t* b) {
    asm("mma.sync.aligned.m16n8k8.row.col.f32.tf32.tf32.f32 "
        "{%0,%1,%2,%3},{%4,%5,%6,%7},{%8,%9},{%0,%1,%2,%3};"
        : "+f"(d[0]), "+f"(d[1]), "+f"(d[2]), "+f"(d[3])
        : "r"(a[0]), "r"(a[1]), "r"(a[2]), "r"(a[3]), "r"(b[0]), "r"(b[1]));
}
__device__ __forceinline__ void cp16(void* dst, const void* src) {
    uint32_t d = (uint32_t)__cvta_generic_to_shared(dst);
    asm volatile("cp.async.cg.shared.global [%0], [%1], 16;" :: "r"(d), "l"(src));
}
__device__ __forceinline__ void cp_commit() {
    asm volatile("cp.async.commit_group;");
}
__device__ __forceinline__ void cp_wait0() {
    asm volatile("cp.async.wait_group 0;" ::: "memory");
}

// ---------------------------------------------------------------------------
// Pre-pass: tf32-round inputs and write k-pair-permuted layouts.
// ---------------------------------------------------------------------------
__global__ void cvt_x(const float4* __restrict__ src) {
    int i = blockIdx.x * 256 + threadIdx.x;
    int idx = 4*i, row = idx >> 10, col = idx & 1023;
    float4 v = src[i];
    float* dst = g_x + (long)row * E_ + (col & ~7) + ((col >> 2) & 1);
    int j2 = 2*(col & 3);
    dst[j2] = tfb(v.x); dst[j2+2] = tfb(v.y);
    dst[j2+4] = tfb(v.z); dst[j2+6] = tfb(v.w);
}
__global__ void cvt_w(const float4* __restrict__ wq, const float4* __restrict__ wk,
                      const float4* __restrict__ wv, const float4* __restrict__ wo) {
    int z = blockIdx.z;
    int i = blockIdx.x * 256 + threadIdx.x;
    const float4* s = (z==0) ? wq : (z==1) ? wk : (z==2) ? wv : wo;
    int idx = 4*i, row = idx >> 10, col = idx & 1023;
    float4 v = s[i];
    float* dst = g_w + (size_t)z*E_*E_ + (long)row * E_ + (col & ~7) + ((col >> 2) & 1);
    int j2 = 2*(col & 3);
    dst[j2] = tfb(v.x); dst[j2+2] = tfb(v.y);
    dst[j2+4] = tfb(v.z); dst[j2+6] = tfb(v.w);
}

// ---------------------------------------------------------------------------
// Pipelined tf32 NT GEMM, mma.sync, LDS.64 fragment loads.
// A and W global layouts are k-pair-permuted, so (k=t, k=t+4) fragment pairs
// are adjacent: one LDS.64 each. Smem row stride 40 words -> conflict-free.
// ISQKV=1: z selects Wq/Wk/Wv; epilogue scatters Q (scaled tf32, natural),
//          K (d-perm), V^T (j-perm).  ISQKV=0: out = g_o @ Wo^T + bo.
// ---------------------------------------------------------------------------
#define GSTRIDE 40
#define GSTAGE  (128*GSTRIDE)          // words per operand-stage
#define GSMEM   (2*2*GSTAGE*4)         // 81920 B

template<int ISQKV>
__global__ void __launch_bounds__(256, 2)
gemm_pipe(const float* __restrict__ b0p, const float* __restrict__ b1p,
          const float* __restrict__ b2p, float* __restrict__ outp)
{
    extern __shared__ uint32_t smg[];
    uint32_t (*As)[128][GSTRIDE] = (uint32_t(*)[128][GSTRIDE])smg;
    uint32_t (*Bs)[128][GSTRIDE] = (uint32_t(*)[128][GSTRIDE])(smg + 2*GSTAGE);

    const int z = ISQKV ? blockIdx.z : 3;
    const float* A = ISQKV ? g_x : g_o;
    const float* W = g_w + (size_t)z * E_*E_;
    const float* bias = ISQKV ? ((z==0) ? b0p : (z==1) ? b1p : b2p) : b0p;

    const int m0 = blockIdx.y * 128, n0 = blockIdx.x * 128;
    const int tid = threadIdx.x, lane = tid & 31, wid = tid >> 5;
    const int g = lane >> 2, t = lane & 3;
    const int wm = (wid >> 2) * 64, wn = (wid & 3) * 32;

    const int mr = tid >> 1, sg = (tid & 1) * 16;
    const float* Asrc = A + (long)(m0 + mr) * E_ + sg;
    const float* Wsrc = W + (long)(n0 + mr) * E_ + sg;

    float acc[4][4][4] = {};

#pragma unroll
    for (int u = 0; u < 4; u++) {
        cp16(&As[0][mr][sg + 4*u], Asrc + 4*u);
        cp16(&Bs[0][mr][sg + 4*u], Wsrc + 4*u);
    }
    cp_commit();

    for (int s = 0; s < 32; s++) {
        cp_wait0();
        __syncthreads();
        if (s < 31) {
            const float* a2 = Asrc + (s+1)*32;
            const float* w2 = Wsrc + (s+1)*32;
            const int nb = (s+1) & 1;
#pragma unroll
            for (int u = 0; u < 4; u++) {
                cp16(&As[nb][mr][sg + 4*u], a2 + 4*u);
                cp16(&Bs[nb][mr][sg + 4*u], w2 + 4*u);
            }
            cp_commit();
        }
        const int bu = s & 1;
#pragma unroll
        for (int ks = 0; ks < 4; ks++) {
            const int kk = ks * 8 + 2*t;
            uint32_t af[4][4], bf[4][2];
#pragma unroll
            for (int mt = 0; mt < 4; mt++) {
                const int mb = wm + mt*16;
                uint2 u0 = *(const uint2*)&As[bu][mb+g  ][kk];
                uint2 u1 = *(const uint2*)&As[bu][mb+g+8][kk];
                af[mt][0] = u0.x; af[mt][1] = u1.x;
                af[mt][2] = u0.y; af[mt][3] = u1.y;
            }
#pragma unroll
            for (int nt = 0; nt < 4; nt++) {
                uint2 ub = *(const uint2*)&Bs[bu][wn+nt*8+g][kk];
                bf[nt][0] = ub.x; bf[nt][1] = ub.y;
            }
#pragma unroll
            for (int mt = 0; mt < 4; mt++)
#pragma unroll
                for (int nt = 0; nt < 4; nt++)
                    mma8(acc[mt][nt], af[mt], bf[nt]);
        }
    }

    // Epilogue
#pragma unroll
    for (int mt = 0; mt < 4; mt++) {
        const int row = m0 + wm + mt*16 + g;
        const int b = row >> 11, l = row & (L_-1);
#pragma unroll
        for (int nt = 0; nt < 4; nt++) {
            const int col = n0 + wn + nt*8 + 2*t;
            const float bb0 = bias[col], bb1 = bias[col+1];
            float v00 = acc[mt][nt][0] + bb0, v01 = acc[mt][nt][1] + bb1;
            float v10 = acc[mt][nt][2] + bb0, v11 = acc[mt][nt][3] + bb1;
            if (!ISQKV) {
                *(float2*)&outp[(long)row * E_ + col]     = make_float2(v00, v01);
                *(float2*)&outp[(long)(row+8) * E_ + col] = make_float2(v10, v11);
            } else {
                const int h = col >> 6, d = col & 63;
                const long bh = b*H_ + h;
                if (z == 0) {            // Q: pre-scaled tf32, natural layout
                    long qb = (bh * L_ + l) * D_ + d;
                    *(float2*)&g_q[qb] =
                        make_float2(tfb(QSCALE*v00), tfb(QSCALE*v01));
                    *(float2*)&g_q[qb + 8*D_] =
                        make_float2(tfb(QSCALE*v10), tfb(QSCALE*v11));
                } else if (z == 1) {     // K: d-permuted tf32
                    long rb = (bh * L_ + l) * D_;
                    int dp0 = kperm(d), dp1 = kperm(d+1);
                    g_k[rb + dp0]        = tfb(v00);
                    g_k[rb + dp1]        = tfb(v01);
                    g_k[rb + 8*D_ + dp0] = tfb(v10);
                    g_k[rb + 8*D_ + dp1] = tfb(v11);
                } else {                  // V: transposed, j-permuted tf32
                    long vb = (bh * D_ + d) * L_;
                    int jp = (l & ~7) + 2*(l&3) + ((l>>2)&1);
                    g_vT[vb + jp]            = tfb(v00);
                    g_vT[vb + L_ + jp]       = tfb(v01);
                    g_vT[vb + jp + 8]        = tfb(v10);
                    g_vT[vb + L_ + jp + 8]   = tfb(v11);
                }
            }
        }
    }
}

// ---------------------------------------------------------------------------
// Flash attention, tf32 mma.sync, 2 m-tiles per warp (32 q-rows) so every
// K/V B-fragment LDS.64 feeds two MMAs -> half the smem traffic per output.
// Block 256 thr = 8 warps = 256 q-rows per (b,h) block; KV tiles of 64,
// cp.async double-buffered. K [j][dperm] / V^T [d][jperm], stride 72.
// ---------------------------------------------------------------------------
#define FSMEM (2*2*64*72*4)    // 73728 B

__global__ void __launch_bounds__(256, 1)
flash_tf32()
{
    extern __shared__ uint32_t smf[];
    uint32_t (*Ks)[64][72] = (uint32_t(*)[64][72])smf;
    uint32_t (*Vs)[64][72] = (uint32_t(*)[64][72])(smf + 2*64*72);

    const int bh = blockIdx.y, b = bh >> 4, h = bh & 15;
    const int i0g = blockIdx.x * 256;
    const int tid = threadIdx.x, lane = tid & 31, w = tid >> 5;
    const int g = lane >> 2, t = lane & 3;
    const int qw = i0g + w * 32;          // m-tile0: qw, m-tile1: qw+16

    const float* Qb = g_q + (long)bh * L_ * D_;
    const float* Kb = g_k + (long)bh * L_ * D_;
    const float* Vb = g_vT + (long)bh * D_ * L_;

    uint32_t qa0[8][4], qa1[8][4];
#pragma unroll
    for (int kc = 0; kc < 8; kc++) {
        qa0[kc][0] = __float_as_uint(Qb[(long)(qw+g)   *D_ + kc*8+t]);
        qa0[kc][1] = __float_as_uint(Qb[(long)(qw+g+8) *D_ + kc*8+t]);
        qa0[kc][2] = __float_as_uint(Qb[(long)(qw+g)   *D_ + kc*8+t+4]);
        qa0[kc][3] = __float_as_uint(Qb[(long)(qw+g+8) *D_ + kc*8+t+4]);
        qa1[kc][0] = __float_as_uint(Qb[(long)(qw+16+g)  *D_ + kc*8+t]);
        qa1[kc][1] = __float_as_uint(Qb[(long)(qw+16+g+8)*D_ + kc*8+t]);
        qa1[kc][2] = __float_as_uint(Qb[(long)(qw+16+g)  *D_ + kc*8+t+4]);
        qa1[kc][3] = __float_as_uint(Qb[(long)(qw+16+g+8)*D_ + kc*8+t+4]);
    }

    float oa0[8][4] = {}, oa1[8][4] = {};
    float m0v = -1e30f, m1v = -1e30f, l0 = 0.f, l1 = 0.f;   // m-tile0
    float m2v = -1e30f, m3v = -1e30f, l2 = 0.f, l3 = 0.f;   // m-tile1

    const int sr = tid >> 2;
    const int cc = tid & 3;

    {
        const float* ksrc = Kb + (long)sr * D_;
        const float* vsrc = Vb + (long)sr * L_;
#pragma unroll
        for (int u = 0; u < 4; u++) {
            int c4 = (cc + 4*u) * 4;
            cp16(&Ks[0][sr][c4], ksrc + c4);
            cp16(&Vs[0][sr][c4], vsrc + c4);
        }
        cp_commit();
    }

    for (int tt = 0; tt < 32; tt++) {
        cp_wait0();
        __syncthreads();
        if (tt < 31) {
            const int j1 = (tt+1) * 64, nb = (tt+1) & 1;
            const float* ksrc = Kb + (long)(j1 + sr) * D_;
            const float* vsrc = Vb + (long)sr * L_ + j1;
#pragma unroll
            for (int u = 0; u < 4; u++) {
                int c4 = (cc + 4*u) * 4;
                cp16(&Ks[nb][sr][c4], ksrc + c4);
                cp16(&Vs[nb][sr][c4], vsrc + c4);
            }
            cp_commit();
        }
        const int bu = tt & 1;

        // S = Q @ K^T for both m-tiles; one K LDS.64 feeds 2 MMAs
        float sf0[8][4] = {}, sf1[8][4] = {};
#pragma unroll
        for (int jn = 0; jn < 8; jn++) {
#pragma unroll
            for (int kc = 0; kc < 8; kc++) {
                uint2 bb = *(const uint2*)&Ks[bu][jn*8+g][kc*8 + 2*t];
                mma8(sf0[jn], qa0[kc], &bb.x);
                mma8(sf1[jn], qa1[kc], &bb.x);
            }
        }

        // Online softmax, independent per m-tile
        float mx0 = -1e30f, mx1 = -1e30f, mx2 = -1e30f, mx3 = -1e30f;
#pragma unroll
        for (int jn = 0; jn < 8; jn++) {
            mx0 = fmaxf(mx0, fmaxf(sf0[jn][0], sf0[jn][1]));
            mx1 = fmaxf(mx1, fmaxf(sf0[jn][2], sf0[jn][3]));
            mx2 = fmaxf(mx2, fmaxf(sf1[jn][0], sf1[jn][1]));
            mx3 = fmaxf(mx3, fmaxf(sf1[jn][2], sf1[jn][3]));
        }
        mx0 = fmaxf(mx0, __shfl_xor_sync(0xffffffffu, mx0, 1));
        mx0 = fmaxf(mx0, __shfl_xor_sync(0xffffffffu, mx0, 2));
        mx1 = fmaxf(mx1, __shfl_xor_sync(0xffffffffu, mx1, 1));
        mx1 = fmaxf(mx1, __shfl_xor_sync(0xffffffffu, mx1, 2));
        mx2 = fmaxf(mx2, __shfl_xor_sync(0xffffffffu, mx2, 1));
        mx2 = fmaxf(mx2, __shfl_xor_sync(0xffffffffu, mx2, 2));
        mx3 = fmaxf(mx3, __shfl_xor_sync(0xffffffffu, mx3, 1));
        mx3 = fmaxf(mx3, __shfl_xor_sync(0xffffffffu, mx3, 2));

        const float n0v = fmaxf(m0v, mx0), n1v = fmaxf(m1v, mx1);
        const float n2v = fmaxf(m2v, mx2), n3v = fmaxf(m3v, mx3);
        const float c0 = ex2(m0v - n0v), c1 = ex2(m1v - n1v);
        const float c2 = ex2(m2v - n2v), c3 = ex2(m3v - n3v);
        m0v = n0v; m1v = n1v; m2v = n2v; m3v = n3v;

        float s0 = 0.f, s1 = 0.f, s2 = 0.f, s3 = 0.f;
#pragma unroll
        for (int jn = 0; jn < 8; jn++) {
            float p00 = ex2(sf0[jn][0] - n0v), p01 = ex2(sf0[jn][1] - n0v);
            float p02 = ex2(sf0[jn][2] - n1v), p03 = ex2(sf0[jn][3] - n1v);
            float p10 = ex2(sf1[jn][0] - n2v), p11 = ex2(sf1[jn][1] - n2v);
            float p12 = ex2(sf1[jn][2] - n3v), p13 = ex2(sf1[jn][3] - n3v);
            s0 += p00 + p01;  s1 += p02 + p03;
            s2 += p10 + p11;  s3 += p12 + p13;
            sf0[jn][0] = __uint_as_float(f2tf(p00));
            sf0[jn][1] = __uint_as_float(f2tf(p01));
            sf0[jn][2] = __uint_as_float(f2tf(p02));
            sf0[jn][3] = __uint_as_float(f2tf(p03));
            sf1[jn][0] = __uint_as_float(f2tf(p10));
            sf1[jn][1] = __uint_as_float(f2tf(p11));
            sf1[jn][2] = __uint_as_float(f2tf(p12));
            sf1[jn][3] = __uint_as_float(f2tf(p13));
        }
        s0 += __shfl_xor_sync(0xffffffffu, s0, 1);
        s0 += __shfl_xor_sync(0xffffffffu, s0, 2);
        s1 += __shfl_xor_sync(0xffffffffu, s1, 1);
        s1 += __shfl_xor_sync(0xffffffffu, s1, 2);
        s2 += __shfl_xor_sync(0xffffffffu, s2, 1);
        s2 += __shfl_xor_sync(0xffffffffu, s2, 2);
        s3 += __shfl_xor_sync(0xffffffffu, s3, 1);
        s3 += __shfl_xor_sync(0xffffffffu, s3, 2);
        l0 = l0 * c0 + s0;  l1 = l1 * c1 + s1;
        l2 = l2 * c2 + s2;  l3 = l3 * c3 + s3;

#pragma unroll
        for (int dn = 0; dn < 8; dn++) {
            oa0[dn][0] *= c0; oa0[dn][1] *= c0;
            oa0[dn][2] *= c1; oa0[dn][3] *= c1;
            oa1[dn][0] *= c2; oa1[dn][1] *= c2;
            oa1[dn][2] *= c3; oa1[dn][3] *= c3;
        }

        // PV: one V LDS.64 feeds 2 MMAs
        const int base = lane & ~3;
        const int sl1 = base | (t >> 1);
        const int sl2 = base | ((t >> 1) + 2);
        const bool odd = (t & 1);
#pragma unroll
        for (int kc = 0; kc < 8; kc++) {
            uint32_t af0[4], af1[4];
            {
                uint32_t v00 = __shfl_sync(0xffffffffu, __float_as_uint(sf0[kc][0]), sl1);
                uint32_t v01 = __shfl_sync(0xffffffffu, __float_as_uint(sf0[kc][1]), sl1);
                uint32_t v02 = __shfl_sync(0xffffffffu, __float_as_uint(sf0[kc][2]), sl1);
                uint32_t v03 = __shfl_sync(0xffffffffu, __float_as_uint(sf0[kc][3]), sl1);
                uint32_t v10 = __shfl_sync(0xffffffffu, __float_as_uint(sf0[kc][0]), sl2);
                uint32_t v11 = __shfl_sync(0xffffffffu, __float_as_uint(sf0[kc][1]), sl2);
                uint32_t v12 = __shfl_sync(0xffffffffu, __float_as_uint(sf0[kc][2]), sl2);
                uint32_t v13 = __shfl_sync(0xffffffffu, __float_as_uint(sf0[kc][3]), sl2);
                af0[0] = odd ? v01 : v00;
                af0[1] = odd ? v03 : v02;
                af0[2] = odd ? v11 : v10;
                af0[3] = odd ? v13 : v12;
            }
            {
                uint32_t v00 = __shfl_sync(0xffffffffu, __float_as_uint(sf1[kc][0]), sl1);
                uint32_t v01 = __shfl_sync(0xffffffffu, __float_as_uint(sf1[kc][1]), sl1);
                uint32_t v02 = __shfl_sync(0xffffffffu, __float_as_uint(sf1[kc][2]), sl1);
                uint32_t v03 = __shfl_sync(0xffffffffu, __float_as_uint(sf1[kc][3]), sl1);
                uint32_t v10 = __shfl_sync(0xffffffffu, __float_as_uint(sf1[kc][0]), sl2);
                uint32_t v11 = __shfl_sync(0xffffffffu, __float_as_uint(sf1[kc][1]), sl2);
                uint32_t v12 = __shfl_sync(0xffffffffu, __float_as_uint(sf1[kc][2]), sl2);
                uint32_t v13 = __shfl_sync(0xffffffffu, __float_as_uint(sf1[kc][3]), sl2);
                af1[0] = odd ? v01 : v00;
                af1[1] = odd ? v03 : v02;
                af1[2] = odd ? v11 : v10;
                af1[3] = odd ? v13 : v12;
            }
#pragma unroll
            for (int dn = 0; dn < 8; dn++) {
                uint2 bb = *(const uint2*)&Vs[bu][dn*8+g][kc*8 + 2*t];
                mma8(oa0[dn], af0, &bb.x);
                mma8(oa1[dn], af1, &bb.x);
            }
        }
    }

    // Normalize; write to g_o (k-pair-permuted cols) for the output GEMM
    const float i0 = 1.f / l0, i1 = 1.f / l1, i2 = 1.f / l2, i3 = 1.f / l3;
    const long r00 = (long)(b*L_ + qw + g)      * E_ + h*D_;
    const long r01 = (long)(b*L_ + qw + g + 8)  * E_ + h*D_;
    const long r10 = (long)(b*L_ + qw + 16 + g)     * E_ + h*D_;
    const long r11 = (long)(b*L_ + qw + 16 + g + 8) * E_ + h*D_;
#pragma unroll
    for (int dn = 0; dn < 8; dn++) {
        const int c0i = dn*8 + kperm(2*t);
        const int c1i = dn*8 + kperm(2*t + 1);
        g_o[r00 + c0i] = tfb(oa0[dn][0]*i0);
        g_o[r00 + c1i] = tfb(oa0[dn][1]*i0);
        g_o[r01 + c0i] = tfb(oa0[dn][2]*i1);
        g_o[r01 + c1i] = tfb(oa0[dn][3]*i1);
        g_o[r10 + c0i] = tfb(oa1[dn][0]*i2);
        g_o[r10 + c1i] = tfb(oa1[dn][1]*i2);
        g_o[r11 + c0i] = tfb(oa1[dn][2]*i3);
        g_o[r11 + c1i] = tfb(oa1[dn][3]*i3);
    }
}

// ---------------------------------------------------------------------------
extern "C" void kernel_launch(void* const* d_in, const int* in_sizes, int n_in,
                              void* d_out, int out_size)
{
    const float* hidden = (const float*)d_in[0];
    const float* Wq = (const float*)d_in[1];
    const float* bq = (const float*)d_in[2];
    const float* Wk = (const float*)d_in[3];
    const float* bk = (const float*)d_in[4];
    const float* Wv = (const float*)d_in[5];
    const float* bv = (const float*)d_in[6];
    const float* Wo = (const float*)d_in[7];
    const float* bo = (const float*)d_in[8];
    float* out = (float*)d_out;

    cudaFuncSetAttribute(gemm_pipe<1>, cudaFuncAttributeMaxDynamicSharedMemorySize, GSMEM);
    cudaFuncSetAttribute(gemm_pipe<0>, cudaFuncAttributeMaxDynamicSharedMemorySize, GSMEM);
    cudaFuncSetAttribute(flash_tf32,   cudaFuncAttributeMaxDynamicSharedMemorySize, FSMEM);

    // 0) Pre-convert to tf32 bits, k-pair-permuted
    cvt_x<<<M_*E_/4/256, 256>>>((const float4*)hidden);
    cvt_w<<<dim3(E_*E_/4/256, 1, 4), 256>>>((const float4*)Wq, (const float4*)Wk,
                                            (const float4*)Wv, (const float4*)Wo);

    // 1) Fused QKV projections (z = 0,1,2)
    gemm_pipe<1><<<dim3(E_/128, M_/128, 3), 256, GSMEM>>>(bq, bk, bv, nullptr);

    // 2) Flash attention (256 q-rows per block)
    flash_tf32<<<dim3(L_/256, B_*H_), 256, FSMEM>>>();

    // 3) Output projection
    gemm_pipe<0><<<dim3(E_/128, M_/128, 1), 256, GSMEM>>>(bo, nullptr, nullptr, out);
}

// round 8
// speedup vs baseline: 7.5515x; 2.1741x over previous
#include <cuda_runtime.h>
#include <cuda_fp16.h>
#include <cstdint>

#define B_ 2
#define L_ 2048
#define E_ 1024
#define H_ 16
#define D_ 64
#define M_ (B_*L_)   // 4096

#define QSCALE 0.18033688011112042f    // 0.125 * log2(e)

// Scratch (__device__ globals, fp16) — aligned for vector access
__device__ __align__(16) __half g_xh [M_*E_];        // fp16(hidden)
__device__ __align__(16) __half g_wh [4*E_*E_];      // fp16 weights Wq,Wk,Wv,Wo
__device__ __align__(16) __half g_qh [B_*H_*L_*D_];  // fp16(qscale*Q) [B,H,L,D]
__device__ __align__(16) __half g_kh [B_*H_*L_*D_];  // fp16 K [B,H,L,D]
__device__ __align__(16) __half g_vTh[B_*H_*D_*L_];  // fp16 V^T [B,H,D,L]
__device__ __align__(16) __half g_oh [B_*L_*E_];     // fp16 attn out [B,L,E]

// ---------------------------------------------------------------------------
__device__ __forceinline__ uint32_t h2u(float a, float b) {
    __half2 h = __floats2half2_rn(a, b);
    return *reinterpret_cast<uint32_t*>(&h);
}
__device__ __forceinline__ float ex2(float x) {
    float r; asm("ex2.approx.f32 %0, %1;" : "=f"(r) : "f"(x)); return r;
}
__device__ __forceinline__ void mma16(float* d, const uint32_t* a,
                                      uint32_t b0, uint32_t b1) {
    asm("mma.sync.aligned.m16n8k16.row.col.f32.f16.f16.f32 "
        "{%0,%1,%2,%3},{%4,%5,%6,%7},{%8,%9},{%0,%1,%2,%3};"
        : "+f"(d[0]), "+f"(d[1]), "+f"(d[2]), "+f"(d[3])
        : "r"(a[0]), "r"(a[1]), "r"(a[2]), "r"(a[3]), "r"(b0), "r"(b1));
}
__device__ __forceinline__ void ldx4(uint32_t* r, uint32_t addr) {
    asm volatile("ldmatrix.sync.aligned.m8n8.x4.shared.b16 {%0,%1,%2,%3}, [%4];"
        : "=r"(r[0]), "=r"(r[1]), "=r"(r[2]), "=r"(r[3]) : "r"(addr));
}
__device__ __forceinline__ void cp16_s(uint32_t dst, const void* src) {
    asm volatile("cp.async.cg.shared.global [%0], [%1], 16;" :: "r"(dst), "l"(src));
}
__device__ __forceinline__ void cp_commit() {
    asm volatile("cp.async.commit_group;");
}
__device__ __forceinline__ void cp_wait0() {
    asm volatile("cp.async.wait_group 0;" ::: "memory");
}

// ---------------------------------------------------------------------------
// Pre-pass: f32 -> fp16, natural layouts.
// ---------------------------------------------------------------------------
__global__ void cvt_x(const float4* __restrict__ src) {
    int i = blockIdx.x * 256 + threadIdx.x;
    float4 v = src[i];
    ((uint2*)g_xh)[i] = make_uint2(h2u(v.x, v.y), h2u(v.z, v.w));
}
__global__ void cvt_w(const float4* __restrict__ wq, const float4* __restrict__ wk,
                      const float4* __restrict__ wv, const float4* __restrict__ wo) {
    int z = blockIdx.z;
    int i = blockIdx.x * 256 + threadIdx.x;
    const float4* s = (z==0) ? wq : (z==1) ? wk : (z==2) ? wv : wo;
    float4 v = s[i];
    ((uint2*)(g_wh + (size_t)z * E_*E_))[i] = make_uint2(h2u(v.x, v.y), h2u(v.z, v.w));
}

// ---------------------------------------------------------------------------
// fp16 NT GEMM: C = A(4096x1024) @ W(1024x1024)^T + bias.
// 128x128 tile, BK=32 halves, cp.async double-buffered, ldmatrix.x4 frags.
// Row stride 20 words (80 B): ldmatrix row addresses hit distinct 16B slots.
// ISQKV=1: z selects Wq/Wk/Wv; epilogue -> g_qh (scaled) / g_kh / g_vTh.
// ISQKV=0: A=g_oh, W=Wo; epilogue -> f32 output + bias.
// ---------------------------------------------------------------------------
#define GSTW 20
#define GSTG (128*GSTW)            // 2560 words per operand-stage
#define GSMEM (4*GSTG*4)           // 40960 B

template<int ISQKV>
__global__ void __launch_bounds__(256, 2)
gemm_h(const float* __restrict__ b0p, const float* __restrict__ b1p,
       const float* __restrict__ b2p, float* __restrict__ outp)
{
    extern __shared__ uint32_t smg[];
    const uint32_t smb = (uint32_t)__cvta_generic_to_shared(smg);

    const int z = ISQKV ? blockIdx.z : 3;
    const __half* A = ISQKV ? g_xh : g_oh;
    const __half* W = g_wh + (size_t)z * E_*E_;
    const float* bias = ISQKV ? ((z==0) ? b0p : (z==1) ? b1p : b2p) : b0p;

    const int m0 = blockIdx.y * 128, n0 = blockIdx.x * 128;
    const int tid = threadIdx.x, lane = tid & 31, wid = tid >> 5;
    const int g = lane >> 2, t = lane & 3;
    const int wm = (wid >> 2) * 64, wn = (wid & 3) * 32;

    // copy roles: row mr (0..127), 2 chunks of 8 halves at ch0, ch0+1
    const int mr = tid >> 1, ch0 = (tid & 1) * 2;
    const __half* Asrc = A + (long)(m0 + mr) * E_ + ch0*8;
    const __half* Wsrc = W + (long)(n0 + mr) * E_ + ch0*8;
    const uint32_t ast = smb + (mr*GSTW + ch0*4) * 4;
    const uint32_t bst = smb + (2*GSTG + mr*GSTW + ch0*4) * 4;

    // ldmatrix lane-fixed parts
    const int mtx = lane >> 3, rl = lane & 7;
    const uint32_t alm = smb + ((wm + (mtx & 1)*8 + rl)*GSTW + (mtx >> 1)*4) * 4;
    const uint32_t blm = smb + (2*GSTG + (wn + (mtx >> 1)*8 + rl)*GSTW + (mtx & 1)*4) * 4;

    float acc[4][4][4] = {};

    // prologue: stage 0
    cp16_s(ast,      Asrc);     cp16_s(ast + 16, Asrc + 8);
    cp16_s(bst,      Wsrc);     cp16_s(bst + 16, Wsrc + 8);
    cp_commit();

    for (int s = 0; s < 32; s++) {
        cp_wait0();
        __syncthreads();
        if (s < 31) {
            const int go = (s+1) * 32;                    // halves
            const uint32_t so = ((s+1) & 1) * (GSTG*4);   // bytes (per operand)
            cp16_s(ast + so,      Asrc + go);
            cp16_s(ast + so + 16, Asrc + go + 8);
            cp16_s(bst + so,      Wsrc + go);
            cp16_s(bst + so + 16, Wsrc + go + 8);
            cp_commit();
        }
        const uint32_t bo = (s & 1) * (GSTG*4);
#pragma unroll
        for (int ks = 0; ks < 2; ks++) {
            uint32_t af[4][4], bf[4][2];
#pragma unroll
            for (int mt = 0; mt < 4; mt++)
                ldx4(af[mt], alm + bo + (mt*16*GSTW + ks*8) * 4);
#pragma unroll
            for (int nt2 = 0; nt2 < 2; nt2++) {
                uint32_t r[4];
                ldx4(r, blm + bo + (nt2*16*GSTW + ks*8) * 4);
                bf[2*nt2][0]   = r[0]; bf[2*nt2][1]   = r[1];
                bf[2*nt2+1][0] = r[2]; bf[2*nt2+1][1] = r[3];
            }
#pragma unroll
            for (int mt = 0; mt < 4; mt++)
#pragma unroll
                for (int nt = 0; nt < 4; nt++)
                    mma16(acc[mt][nt], af[mt], bf[nt][0], bf[nt][1]);
        }
    }

    // Epilogue
#pragma unroll
    for (int mt = 0; mt < 4; mt++) {
        const int row = m0 + wm + mt*16 + g;
        const int b = row >> 11, l = row & (L_-1);
#pragma unroll
        for (int nt = 0; nt < 4; nt++) {
            const int col = n0 + wn + nt*8 + 2*t;
            const float bb0 = bias[col], bb1 = bias[col+1];
            float v00 = acc[mt][nt][0] + bb0, v01 = acc[mt][nt][1] + bb1;
            float v10 = acc[mt][nt][2] + bb0, v11 = acc[mt][nt][3] + bb1;
            if (!ISQKV) {
                *(float2*)&outp[(long)row * E_ + col]     = make_float2(v00, v01);
                *(float2*)&outp[(long)(row+8) * E_ + col] = make_float2(v10, v11);
            } else {
                const int h = col >> 6, d = col & 63;
                const long bh = b*H_ + h;
                if (z == 0) {            // Q: pre-scaled fp16
                    long qb = (bh * L_ + l) * D_ + d;
                    *(uint32_t*)&g_qh[qb]        = h2u(QSCALE*v00, QSCALE*v01);
                    *(uint32_t*)&g_qh[qb + 8*D_] = h2u(QSCALE*v10, QSCALE*v11);
                } else if (z == 1) {     // K: natural fp16
                    long kb = (bh * L_ + l) * D_ + d;
                    *(uint32_t*)&g_kh[kb]        = h2u(v00, v01);
                    *(uint32_t*)&g_kh[kb + 8*D_] = h2u(v10, v11);
                } else {                  // V^T: [bh][d][l]
                    long vb = (bh * D_ + d) * L_ + l;
                    g_vTh[vb]          = __float2half_rn(v00);
                    g_vTh[vb + L_]     = __float2half_rn(v01);
                    g_vTh[vb + 8]      = __float2half_rn(v10);
                    g_vTh[vb + L_ + 8] = __float2half_rn(v11);
                }
            }
        }
    }
}

// ---------------------------------------------------------------------------
// Flash attention, fp16 m16n8k16. Block 256 = 8 warps x 16 q-rows = 128 rows
// per (b,h) block; KV tiles of 64, cp.async double-buffered.
// K tile [j][d] / V^T tile [d][j], stride 36 words: ldmatrix conflict-free.
// PV A-fragments come directly from S C-fragments (no shuffles).
// ---------------------------------------------------------------------------
#define FSTW 36
#define FTLG (64*FSTW)             // 2304 words per tile
#define FSMEM (4*FTLG*4)           // 36864 B

__global__ void __launch_bounds__(256, 2)
flash_h()
{
    extern __shared__ uint32_t smf[];
    const uint32_t smb = (uint32_t)__cvta_generic_to_shared(smf);

    const int bh = blockIdx.y, b = bh >> 4, h = bh & 15;
    const int i0g = blockIdx.x * 128;
    const int tid = threadIdx.x, lane = tid & 31, w = tid >> 5;
    const int g = lane >> 2, t = lane & 3;
    const int qw = i0g + w * 16;

    const __half* Qh = g_qh + (long)bh * L_ * D_;
    const __half* Kh = g_kh + (long)bh * L_ * D_;
    const __half* Vh = g_vTh + (long)bh * D_ * L_;

    // Q A-fragments: 4 k16-chunks x 4 regs (already scaled fp16)
    uint32_t qa[4][4];
#pragma unroll
    for (int kc = 0; kc < 4; kc++) {
        qa[kc][0] = *(const uint32_t*)&Qh[(long)(qw+g)  *D_ + kc*16 + 2*t];
        qa[kc][1] = *(const uint32_t*)&Qh[(long)(qw+g+8)*D_ + kc*16 + 2*t];
        qa[kc][2] = *(const uint32_t*)&Qh[(long)(qw+g)  *D_ + kc*16 + 2*t + 8];
        qa[kc][3] = *(const uint32_t*)&Qh[(long)(qw+g+8)*D_ + kc*16 + 2*t + 8];
    }

    float oa[8][4] = {};
    float m0v = -1e30f, m1v = -1e30f, l0 = 0.f, l1 = 0.f;

    // copy roles: row fr (0..63), 2 chunks of 8 halves at ch0, ch0+1
    const int fr = tid >> 2, ch0 = (tid & 3) * 2;
    const uint32_t kst = smb + (fr*FSTW + ch0*4) * 4;
    const uint32_t vst = smb + (2*FTLG + fr*FSTW + ch0*4) * 4;

    // ldmatrix lane-fixed parts
    const int mtx = lane >> 3, rl = lane & 7;
    const uint32_t klm = smb + (((mtx >> 1)*8 + rl)*FSTW + (mtx & 1)*4) * 4;
    const uint32_t vlm = klm + 2*FTLG*4;

    // prologue: tile 0
    {
        const __half* ks = Kh + (long)fr * D_ + ch0*8;
        const __half* vs = Vh + (long)fr * L_ + ch0*8;
        cp16_s(kst,      ks);  cp16_s(kst + 16, ks + 8);
        cp16_s(vst,      vs);  cp16_s(vst + 16, vs + 8);
        cp_commit();
    }

    for (int tt = 0; tt < 32; tt++) {
        cp_wait0();
        __syncthreads();
        if (tt < 31) {
            const int j1 = (tt+1) * 64;
            const uint32_t so = ((tt+1) & 1) * (FTLG*4);
            const __half* ks = Kh + (long)(j1 + fr) * D_ + ch0*8;
            const __half* vs = Vh + (long)fr * L_ + j1 + ch0*8;
            cp16_s(kst + so,      ks);  cp16_s(kst + so + 16, ks + 8);
            cp16_s(vst + so,      vs);  cp16_s(vst + so + 16, vs + 8);
            cp_commit();
        }
        const uint32_t bo = (tt & 1) * (FTLG*4);

        // S = Q @ K^T
        float sf[8][4] = {};
#pragma unroll
        for (int jn2 = 0; jn2 < 4; jn2++) {
#pragma unroll
            for (int kc = 0; kc < 4; kc++) {
                uint32_t r[4];
                ldx4(r, klm + bo + (jn2*16*FSTW + kc*8) * 4);
                mma16(sf[2*jn2],   qa[kc], r[0], r[1]);
                mma16(sf[2*jn2+1], qa[kc], r[2], r[3]);
            }
        }

        // Online softmax (log2 domain; stats within each quad)
        float mx0 = -1e30f, mx1 = -1e30f;
#pragma unroll
        for (int jn = 0; jn < 8; jn++) {
            mx0 = fmaxf(mx0, fmaxf(sf[jn][0], sf[jn][1]));
            mx1 = fmaxf(mx1, fmaxf(sf[jn][2], sf[jn][3]));
        }
        mx0 = fmaxf(mx0, __shfl_xor_sync(0xffffffffu, mx0, 1));
        mx0 = fmaxf(mx0, __shfl_xor_sync(0xffffffffu, mx0, 2));
        mx1 = fmaxf(mx1, __shfl_xor_sync(0xffffffffu, mx1, 1));
        mx1 = fmaxf(mx1, __shfl_xor_sync(0xffffffffu, mx1, 2));

        const float n0v = fmaxf(m0v, mx0), n1v = fmaxf(m1v, mx1);
        const float c0 = ex2(m0v - n0v),   c1 = ex2(m1v - n1v);
        m0v = n0v; m1v = n1v;

        float s0 = 0.f, s1 = 0.f;
        uint32_t ph[8][2];
#pragma unroll
        for (int jn = 0; jn < 8; jn++) {
            float p0 = ex2(sf[jn][0] - n0v);
            float p1 = ex2(sf[jn][1] - n0v);
            float p2 = ex2(sf[jn][2] - n1v);
            float p3 = ex2(sf[jn][3] - n1v);
            s0 += p0 + p1;  s1 += p2 + p3;
            ph[jn][0] = h2u(p0, p1);
            ph[jn][1] = h2u(p2, p3);
        }
        s0 += __shfl_xor_sync(0xffffffffu, s0, 1);
        s0 += __shfl_xor_sync(0xffffffffu, s0, 2);
        s1 += __shfl_xor_sync(0xffffffffu, s1, 1);
        s1 += __shfl_xor_sync(0xffffffffu, s1, 2);
        l0 = l0 * c0 + s0;
        l1 = l1 * c1 + s1;

#pragma unroll
        for (int dn = 0; dn < 8; dn++) {
            oa[dn][0] *= c0; oa[dn][1] *= c0;
            oa[dn][2] *= c1; oa[dn][3] *= c1;
        }

        // PV: A-fragments straight from S fragments, V via ldmatrix
#pragma unroll
        for (int dn2 = 0; dn2 < 4; dn2++) {
#pragma unroll
            for (int kc = 0; kc < 4; kc++) {
                uint32_t pt[4] = { ph[2*kc][0], ph[2*kc][1],
                                   ph[2*kc+1][0], ph[2*kc+1][1] };
                uint32_t r[4];
                ldx4(r, vlm + bo + (dn2*16*FSTW + kc*8) * 4);
                mma16(oa[2*dn2],   pt, r[0], r[1]);
                mma16(oa[2*dn2+1], pt, r[2], r[3]);
            }
        }
    }

    // Normalize; write fp16 to g_oh [B,L,E] at column h*64
    const float i0 = 1.f / l0, i1 = 1.f / l1;
    const long r0 = (long)(b*L_ + qw + g)     * E_ + h*D_;
    const long r1 = (long)(b*L_ + qw + g + 8) * E_ + h*D_;
#pragma unroll
    for (int dn = 0; dn < 8; dn++) {
        const int col = dn*8 + 2*t;
        *(uint32_t*)&g_oh[r0 + col] = h2u(oa[dn][0]*i0, oa[dn][1]*i0);
        *(uint32_t*)&g_oh[r1 + col] = h2u(oa[dn][2]*i1, oa[dn][3]*i1);
    }
}

// ---------------------------------------------------------------------------
extern "C" void kernel_launch(void* const* d_in, const int* in_sizes, int n_in,
                              void* d_out, int out_size)
{
    const float* hidden = (const float*)d_in[0];
    const float* Wq = (const float*)d_in[1];
    const float* bq = (const float*)d_in[2];
    const float* Wk = (const float*)d_in[3];
    const float* bk = (const float*)d_in[4];
    const float* Wv = (const float*)d_in[5];
    const float* bv = (const float*)d_in[6];
    const float* Wo = (const float*)d_in[7];
    const float* bo = (const float*)d_in[8];
    float* out = (float*)d_out;

    cudaFuncSetAttribute(gemm_h<1>, cudaFuncAttributeMaxDynamicSharedMemorySize, GSMEM);
    cudaFuncSetAttribute(gemm_h<0>, cudaFuncAttributeMaxDynamicSharedMemorySize, GSMEM);
    cudaFuncSetAttribute(flash_h,   cudaFuncAttributeMaxDynamicSharedMemorySize, FSMEM);

    // 0) Convert inputs to fp16
    cvt_x<<<M_*E_/4/256, 256>>>((const float4*)hidden);
    cvt_w<<<dim3(E_*E_/4/256, 1, 4), 256>>>((const float4*)Wq, (const float4*)Wk,
                                            (const float4*)Wv, (const float4*)Wo);

    // 1) Fused QKV projections (z = 0,1,2)
    gemm_h<1><<<dim3(E_/128, M_/128, 3), 256, GSMEM>>>(bq, bk, bv, nullptr);

    // 2) Flash attention
    flash_h<<<dim3(L_/128, B_*H_), 256, FSMEM>>>();

    // 3) Output projection
    gemm_h<0><<<dim3(E_/128, M_/128, 1), 256, GSMEM>>>(bo, nullptr, nullptr, out);
}